// round 9
// baseline (speedup 1.0000x reference)
#include <cuda_runtime.h>
#include <cstdint>

#define NN 100000
#define NE 1600000
#define F1 128
#define F2 64

// ---- scratch: __device__ globals, device-code references only ----
__device__ int   g_is64;
__device__ int   g_cnt[NN];
__device__ int   g_rowptr[NN];
__device__ int   g_wpos[NN];
__device__ int   g_adj[NE];
__device__ float g_dinv[NN];
__device__ float g_t1s[(size_t)NN * F1];
__device__ float g_agg1[(size_t)NN * F1];
__device__ float g_t2s[(size_t)NN * F2];

// ---------------- dtype detection / CSR build ----------------
__global__ void detect_kernel(const void* ei, int n, int e) {
    __shared__ int bad;
    if (threadIdx.x == 0) bad = 0;
    __syncthreads();
    const long long* p = (const long long*)ei;
    for (int i = threadIdx.x; i < 1024 && i < e; i += blockDim.x) {
        long long v = p[i];
        if (v < 0 || v >= n) bad = 1;
    }
    __syncthreads();
    if (threadIdx.x == 0) g_is64 = (bad == 0) ? 1 : 0;
}

__global__ void zero_cnt_kernel(int n) {
    int i = blockIdx.x * blockDim.x + threadIdx.x;
    if (i < n) g_cnt[i] = 0;
}

__global__ void count_kernel(const void* ei, int e) {
    int i = blockIdx.x * blockDim.x + threadIdx.x;
    if (i >= e) return;
    int d = g_is64 ? (int)((const long long*)ei)[(size_t)e + i]
                   : ((const int*)ei)[(size_t)e + i];
    atomicAdd(&g_cnt[d], 1);
}

__global__ void dinv_kernel(int n) {
    int i = blockIdx.x * blockDim.x + threadIdx.x;
    if (i < n) g_dinv[i] = rsqrtf((float)(g_cnt[i] + 1));
}

__global__ void scan_kernel(int n) {
    __shared__ int sums[1024];
    const int tid = threadIdx.x;
    const int ITEMS = (n + 1023) / 1024;
    int start = tid * ITEMS;
    int end = min(start + ITEMS, n);
    int s = 0;
    for (int i = start; i < end; i++) s += g_cnt[i];
    sums[tid] = s;
    __syncthreads();
    for (int off = 1; off < 1024; off <<= 1) {
        int v = (tid >= off) ? sums[tid - off] : 0;
        __syncthreads();
        sums[tid] += v;
        __syncthreads();
    }
    int prefix = (tid == 0) ? 0 : sums[tid - 1];
    for (int i = start; i < end; i++) {
        g_rowptr[i] = prefix;
        g_wpos[i]   = prefix;
        prefix += g_cnt[i];
    }
}

__global__ void fill_kernel(const void* ei, int e) {
    int i = blockIdx.x * blockDim.x + threadIdx.x;
    if (i >= e) return;
    int s, d;
    if (g_is64) {
        const long long* p = (const long long*)ei;
        s = (int)p[i];
        d = (int)p[(size_t)e + i];
    } else {
        const int* p = (const int*)ei;
        s = p[i];
        d = p[(size_t)e + i];
    }
    int pos = atomicAdd(&g_wpos[d], 1);
    g_adj[pos] = s;
}

// ---------------- tf32 tensor-core GEMM ----------------
__device__ __forceinline__ float f2tf32(float f) {
    unsigned r;
    asm("cvt.rna.tf32.f32 %0, %1;" : "=r"(r) : "f"(f));
    return __uint_as_float(r);
}

__device__ __forceinline__ void mma_tf32(float* c, const unsigned* a, const unsigned* b) {
    asm volatile("mma.sync.aligned.m16n8k8.row.col.f32.tf32.tf32.f32 "
                 "{%0,%1,%2,%3}, {%4,%5,%6,%7}, {%8,%9}, {%0,%1,%2,%3};"
                 : "+f"(c[0]), "+f"(c[1]), "+f"(c[2]), "+f"(c[3])
                 : "r"(a[0]), "r"(a[1]), "r"(a[2]), "r"(a[3]),
                   "r"(b[0]), "r"(b[1]));
}

// t[r,c] = sum_k X[r,k] * W[c,k]; epilogue: outS = t * dinv[r]
// LAYER1: X = x arg, out = g_t1s, BM=64, FOUT=128, warps 2x4.
// !LAYER1: X = relu(g_agg1 + b1), out = g_t2s, BM=128, FOUT=64, warps 4x2.
template<bool LAYER1>
__global__ void gemm_tc(const float* __restrict__ Xarg,
                        const float* __restrict__ W,
                        const float* __restrict__ bias,
                        int n) {
    constexpr int FOUT = LAYER1 ? F1 : F2;
    constexpr int BM   = LAYER1 ? 64 : 128;
    constexpr int WC   = LAYER1 ? 4 : 2;     // warp-cols (x32)
    constexpr int XS   = 132;                 // Xs stride (pad 4)
    constexpr int WS   = FOUT + 8;            // Ws stride (pad 8)

    extern __shared__ float smem[];
    float* Xs = smem;                  // [BM][XS]
    float* Ws = smem + BM * XS;        // [128][WS]

    const float* X = LAYER1 ? Xarg : (const float*)g_agg1;
    float* outS = LAYER1 ? (float*)g_t1s : (float*)g_t2s;

    const int tid = threadIdx.x;
    const int row0 = blockIdx.x * BM;

    // --- stage X tile (BM x 128), tf32-rounded; layer2 fuses bias+relu ---
    for (int idx = tid; idx < BM * 32; idx += 256) {
        int r = idx >> 5;
        int k4 = (idx & 31) * 4;
        int gr = row0 + r;
        float4 v = make_float4(0.f, 0.f, 0.f, 0.f);
        if (gr < n) v = *(const float4*)&X[(size_t)gr * 128 + k4];
        if (!LAYER1) {
            v.x = fmaxf(v.x + bias[k4 + 0], 0.f);
            v.y = fmaxf(v.y + bias[k4 + 1], 0.f);
            v.z = fmaxf(v.z + bias[k4 + 2], 0.f);
            v.w = fmaxf(v.w + bias[k4 + 3], 0.f);
        }
        float4 t = make_float4(f2tf32(v.x), f2tf32(v.y), f2tf32(v.z), f2tf32(v.w));
        *(float4*)&Xs[r * XS + k4] = t;
    }
    // --- stage W transposed into Ws[k][c], tf32-rounded ---
    for (int idx = tid; idx < FOUT * 32; idx += 256) {
        int c = idx >> 5;
        int k4 = (idx & 31) * 4;
        float4 v = *(const float4*)&W[(size_t)c * 128 + k4];
        Ws[(k4 + 0) * WS + c] = f2tf32(v.x);
        Ws[(k4 + 1) * WS + c] = f2tf32(v.y);
        Ws[(k4 + 2) * WS + c] = f2tf32(v.z);
        Ws[(k4 + 3) * WS + c] = f2tf32(v.w);
    }
    __syncthreads();

    // --- warp tiles: 32 rows x 32 cols each ---
    const int w = tid >> 5;
    const int lane = tid & 31;
    const int wr = w / WC;            // warp row index
    const int wc = w % WC;            // warp col index
    const int wrow = wr * 32;
    const int wcol = wc * 32;
    const int qr = lane >> 2;         // 0..7
    const int qc = lane & 3;          // 0..3

    float acc[2][4][4];
#pragma unroll
    for (int rt = 0; rt < 2; rt++)
#pragma unroll
        for (int ct = 0; ct < 4; ct++)
#pragma unroll
            for (int i = 0; i < 4; i++) acc[rt][ct][i] = 0.f;

#pragma unroll 4
    for (int k0 = 0; k0 < 128; k0 += 8) {
        unsigned a[2][4];
#pragma unroll
        for (int rt = 0; rt < 2; rt++) {
            const float* xb = &Xs[(wrow + rt * 16 + qr) * XS + k0 + qc];
            a[rt][0] = __float_as_uint(xb[0]);
            a[rt][1] = __float_as_uint(xb[8 * XS]);
            a[rt][2] = __float_as_uint(xb[4]);
            a[rt][3] = __float_as_uint(xb[8 * XS + 4]);
        }
        unsigned b[4][2];
#pragma unroll
        for (int ct = 0; ct < 4; ct++) {
            const float* wb = &Ws[(k0 + qc) * WS + wcol + ct * 8 + qr];
            b[ct][0] = __float_as_uint(wb[0]);
            b[ct][1] = __float_as_uint(wb[4 * WS]);
        }
#pragma unroll
        for (int rt = 0; rt < 2; rt++)
#pragma unroll
            for (int ct = 0; ct < 4; ct++)
                mma_tf32(acc[rt][ct], a[rt], b[ct]);
    }

    // --- epilogue: scale by dinv[row], store float2 pairs ---
#pragma unroll
    for (int rt = 0; rt < 2; rt++) {
        int r0 = row0 + wrow + rt * 16 + qr;
        int r1 = r0 + 8;
        float d0 = (r0 < n) ? g_dinv[r0] : 0.f;
        float d1 = (r1 < n) ? g_dinv[r1] : 0.f;
#pragma unroll
        for (int ct = 0; ct < 4; ct++) {
            int col = wcol + ct * 8 + qc * 2;
            if (r0 < n)
                *(float2*)&outS[(size_t)r0 * FOUT + col] =
                    make_float2(acc[rt][ct][0] * d0, acc[rt][ct][1] * d0);
            if (r1 < n)
                *(float2*)&outS[(size_t)r1 * FOUT + col] =
                    make_float2(acc[rt][ct][2] * d1, acc[rt][ct][3] * d1);
        }
    }
}

// ---------------- CSR aggregation (atomic-free, MLP-unrolled) ----------------
__global__ void agg1_kernel(int n) {
    int w = (blockIdx.x * blockDim.x + threadIdx.x) >> 5;
    if (w >= n) return;
    int lane = threadIdx.x & 31;
    int c = lane * 4;
    float4 acc = *(const float4*)&g_t1s[(size_t)w * F1 + c];   // self-loop
    int beg = g_rowptr[w];
    int cnt = g_cnt[w];
    int j = 0;
    for (; j + 4 <= cnt; j += 4) {
        int s0 = g_adj[beg + j + 0];
        int s1 = g_adj[beg + j + 1];
        int s2 = g_adj[beg + j + 2];
        int s3 = g_adj[beg + j + 3];
        float4 v0 = *(const float4*)&g_t1s[(size_t)s0 * F1 + c];
        float4 v1 = *(const float4*)&g_t1s[(size_t)s1 * F1 + c];
        float4 v2 = *(const float4*)&g_t1s[(size_t)s2 * F1 + c];
        float4 v3 = *(const float4*)&g_t1s[(size_t)s3 * F1 + c];
        acc.x += v0.x + v1.x + v2.x + v3.x;
        acc.y += v0.y + v1.y + v2.y + v3.y;
        acc.z += v0.z + v1.z + v2.z + v3.z;
        acc.w += v0.w + v1.w + v2.w + v3.w;
    }
    for (; j < cnt; j++) {
        int src = g_adj[beg + j];
        float4 v = *(const float4*)&g_t1s[(size_t)src * F1 + c];
        acc.x += v.x; acc.y += v.y; acc.z += v.z; acc.w += v.w;
    }
    float di = g_dinv[w];
    *(float4*)&g_agg1[(size_t)w * F1 + c] =
        make_float4(acc.x*di, acc.y*di, acc.z*di, acc.w*di);
}

__global__ void agg2_kernel(const float* __restrict__ b2, float* __restrict__ out, int n) {
    int h = (blockIdx.x * blockDim.x + threadIdx.x) >> 4;
    if (h >= n) return;
    int lane = threadIdx.x & 15;
    int c = lane * 4;
    float4 acc = *(const float4*)&g_t2s[(size_t)h * F2 + c];   // self-loop
    int beg = g_rowptr[h];
    int cnt = g_cnt[h];
    int j = 0;
    for (; j + 4 <= cnt; j += 4) {
        int s0 = g_adj[beg + j + 0];
        int s1 = g_adj[beg + j + 1];
        int s2 = g_adj[beg + j + 2];
        int s3 = g_adj[beg + j + 3];
        float4 v0 = *(const float4*)&g_t2s[(size_t)s0 * F2 + c];
        float4 v1 = *(const float4*)&g_t2s[(size_t)s1 * F2 + c];
        float4 v2 = *(const float4*)&g_t2s[(size_t)s2 * F2 + c];
        float4 v3 = *(const float4*)&g_t2s[(size_t)s3 * F2 + c];
        acc.x += v0.x + v1.x + v2.x + v3.x;
        acc.y += v0.y + v1.y + v2.y + v3.y;
        acc.z += v0.z + v1.z + v2.z + v3.z;
        acc.w += v0.w + v1.w + v2.w + v3.w;
    }
    for (; j < cnt; j++) {
        int src = g_adj[beg + j];
        float4 v = *(const float4*)&g_t2s[(size_t)src * F2 + c];
        acc.x += v.x; acc.y += v.y; acc.z += v.z; acc.w += v.w;
    }
    float di = g_dinv[h];
    *(float4*)&out[(size_t)h * F2 + c] =
        make_float4(acc.x*di + b2[c+0], acc.y*di + b2[c+1],
                    acc.z*di + b2[c+2], acc.w*di + b2[c+3]);
}

// ---------------- launch ----------------
extern "C" void kernel_launch(void* const* d_in, const int* in_sizes, int n_in,
                              void* d_out, int out_size) {
    const float* x  = (const float*)d_in[0];
    const void*  ei = d_in[1];
    const float* W1 = (const float*)d_in[2];
    const float* b1 = (const float*)d_in[3];
    const float* W2 = (const float*)d_in[4];
    const float* b2 = (const float*)d_in[5];
    float* out = (float*)d_out;

    const int n = in_sizes[0] / F1;       // 100000
    const int e = in_sizes[1] / 2;        // 1600000

    const int T = 256;
    // CSR build + norms
    detect_kernel<<<1, 256>>>(ei, n, e);
    zero_cnt_kernel<<<(n + T - 1) / T, T>>>(n);
    count_kernel<<<(e + T - 1) / T, T>>>(ei, e);
    dinv_kernel<<<(n + T - 1) / T, T>>>(n);
    scan_kernel<<<1, 1024>>>(n);
    fill_kernel<<<(e + T - 1) / T, T>>>(ei, e);

    // dynamic smem: L1: Xs 64*132 + Ws 128*136 floats; L2: Xs 128*132 + Ws 128*72
    const int SMEM1 = (64 * 132 + 128 * (F1 + 8)) * 4;
    const int SMEM2 = (128 * 132 + 128 * (F2 + 8)) * 4;
    cudaFuncSetAttribute(gemm_tc<true>,  cudaFuncAttributeMaxDynamicSharedMemorySize, SMEM1);
    cudaFuncSetAttribute(gemm_tc<false>, cudaFuncAttributeMaxDynamicSharedMemorySize, SMEM2);

    // layer 1
    gemm_tc<true><<<(n + 63) / 64, 256, SMEM1>>>(x, W1, nullptr, n);
    agg1_kernel<<<(n * 32 + T - 1) / T, T>>>(n);

    // layer 2
    gemm_tc<false><<<(n + 127) / 128, 256, SMEM2>>>(nullptr, W2, b1, n);
    agg2_kernel<<<(n * 16 + T - 1) / T, T>>>(b2, out, n);
}

// round 10
// speedup vs baseline: 1.3535x; 1.3535x over previous
#include <cuda_runtime.h>
#include <cstdint>

#define NN 100000
#define NE 1600000
#define F1 128
#define F2 64

// ---- scratch: __device__ globals, device-code references only ----
__device__ int   g_is64;
__device__ int   g_cnt[NN];
__device__ int   g_rowptr[NN];
__device__ int   g_wpos[NN];
__device__ int   g_adj[NE];
__device__ float g_dinv[NN];
__device__ float g_t1s[(size_t)NN * F1];
__device__ float g_agg1[(size_t)NN * F1];
__device__ float g_t2s[(size_t)NN * F2];

// ---------------- dtype detection / CSR build ----------------
__global__ void detect_kernel(const void* ei, int n, int e) {
    __shared__ int bad;
    if (threadIdx.x == 0) bad = 0;
    __syncthreads();
    const long long* p = (const long long*)ei;
    for (int i = threadIdx.x; i < 1024 && i < e; i += blockDim.x) {
        long long v = p[i];
        if (v < 0 || v >= n) bad = 1;
    }
    __syncthreads();
    if (threadIdx.x == 0) g_is64 = (bad == 0) ? 1 : 0;
}

__global__ void zero_cnt_kernel(int n) {
    int i = blockIdx.x * blockDim.x + threadIdx.x;
    if (i < n) g_cnt[i] = 0;
}

__global__ void count_kernel(const void* ei, int e) {
    int i = blockIdx.x * blockDim.x + threadIdx.x;
    if (i >= e) return;
    int d = g_is64 ? (int)((const long long*)ei)[(size_t)e + i]
                   : ((const int*)ei)[(size_t)e + i];
    atomicAdd(&g_cnt[d], 1);
}

__global__ void dinv_kernel(int n) {
    int i = blockIdx.x * blockDim.x + threadIdx.x;
    if (i < n) g_dinv[i] = rsqrtf((float)(g_cnt[i] + 1));
}

__global__ void scan_kernel(int n) {
    __shared__ int sums[1024];
    const int tid = threadIdx.x;
    const int ITEMS = (n + 1023) / 1024;
    int start = tid * ITEMS;
    int end = min(start + ITEMS, n);
    int s = 0;
    for (int i = start; i < end; i++) s += g_cnt[i];
    sums[tid] = s;
    __syncthreads();
    for (int off = 1; off < 1024; off <<= 1) {
        int v = (tid >= off) ? sums[tid - off] : 0;
        __syncthreads();
        sums[tid] += v;
        __syncthreads();
    }
    int prefix = (tid == 0) ? 0 : sums[tid - 1];
    for (int i = start; i < end; i++) {
        g_rowptr[i] = prefix;
        g_wpos[i]   = prefix;
        prefix += g_cnt[i];
    }
}

__global__ void fill_kernel(const void* ei, int e) {
    int i = blockIdx.x * blockDim.x + threadIdx.x;
    if (i >= e) return;
    int s, d;
    if (g_is64) {
        const long long* p = (const long long*)ei;
        s = (int)p[i];
        d = (int)p[(size_t)e + i];
    } else {
        const int* p = (const int*)ei;
        s = p[i];
        d = p[(size_t)e + i];
    }
    int pos = atomicAdd(&g_wpos[d], 1);
    g_adj[pos] = s;
}

// ---------------- tf32 tensor-core GEMM (k-chunked) ----------------
__device__ __forceinline__ float f2tf32(float f) {
    unsigned r;
    asm("cvt.rna.tf32.f32 %0, %1;" : "=r"(r) : "f"(f));
    return __uint_as_float(r);
}

__device__ __forceinline__ void mma_tf32(float* c, const unsigned* a, const unsigned* b) {
    asm volatile("mma.sync.aligned.m16n8k8.row.col.f32.tf32.tf32.f32 "
                 "{%0,%1,%2,%3}, {%4,%5,%6,%7}, {%8,%9}, {%0,%1,%2,%3};"
                 : "+f"(c[0]), "+f"(c[1]), "+f"(c[2]), "+f"(c[3])
                 : "r"(a[0]), "r"(a[1]), "r"(a[2]), "r"(a[3]),
                   "r"(b[0]), "r"(b[1]));
}

// t[r,c] = sum_k X[r,k]*W[c,k]; epilogue outS = t * dinv[r].
// BM=128, 256 threads = 8 warps in 4x2. Warp tile: 32 x (NT*8).
// KC=32 k-chunk; Xs[128][36], Ws[FOUT][36] (W native [c][k] = col-major B).
template<bool LAYER1>
__global__ void gemm_tc(const float* __restrict__ Xarg,
                        const float* __restrict__ W,
                        const float* __restrict__ bias,
                        int n) {
    constexpr int FOUT = LAYER1 ? F1 : F2;
    constexpr int NT   = LAYER1 ? 8 : 4;      // n8-tiles per warp
    constexpr int KC   = 32;
    constexpr int ST   = KC + 4;              // stride 36

    __shared__ float Xs[128 * ST];
    __shared__ float Ws[FOUT * ST];

    const float* X = LAYER1 ? Xarg : (const float*)g_agg1;
    float* outS = LAYER1 ? (float*)g_t1s : (float*)g_t2s;

    const int tid = threadIdx.x;
    const int row0 = blockIdx.x * 128;
    const int w = tid >> 5;
    const int lane = tid & 31;
    const int wrow = (w >> 1) * 32;           // 4 warp-rows
    const int wcol = (w & 1) * (NT * 8);      // 2 warp-cols
    const int qr = lane >> 2;
    const int qc = lane & 3;

    float acc[2][NT][4];
#pragma unroll
    for (int rt = 0; rt < 2; rt++)
#pragma unroll
        for (int ct = 0; ct < NT; ct++)
#pragma unroll
            for (int i = 0; i < 4; i++) acc[rt][ct][i] = 0.f;

    for (int k0 = 0; k0 < 128; k0 += KC) {
        // stage X chunk: 128 x KC (1024 float4)
#pragma unroll
        for (int it = 0; it < 4; it++) {
            int idx = tid + it * 256;
            int r = idx >> 3;
            int k4 = (idx & 7) * 4;
            int gr = row0 + r;
            float4 v = make_float4(0.f, 0.f, 0.f, 0.f);
            if (gr < n) v = *(const float4*)&X[(size_t)gr * 128 + k0 + k4];
            if (!LAYER1) {
                v.x = fmaxf(v.x + bias[k0 + k4 + 0], 0.f);
                v.y = fmaxf(v.y + bias[k0 + k4 + 1], 0.f);
                v.z = fmaxf(v.z + bias[k0 + k4 + 2], 0.f);
                v.w = fmaxf(v.w + bias[k0 + k4 + 3], 0.f);
            }
            *(float4*)&Xs[r * ST + k4] =
                make_float4(f2tf32(v.x), f2tf32(v.y), f2tf32(v.z), f2tf32(v.w));
        }
        // stage W chunk: FOUT x KC, native [c][k] layout (no transpose)
#pragma unroll
        for (int it = 0; it < FOUT / 32; it++) {
            int idx = tid + it * 256;
            int c = idx >> 3;
            int k4 = (idx & 7) * 4;
            float4 v = *(const float4*)&W[(size_t)c * 128 + k0 + k4];
            *(float4*)&Ws[c * ST + k4] =
                make_float4(f2tf32(v.x), f2tf32(v.y), f2tf32(v.z), f2tf32(v.w));
        }
        __syncthreads();

#pragma unroll
        for (int kk = 0; kk < KC; kk += 8) {
            unsigned a[2][4];
#pragma unroll
            for (int rt = 0; rt < 2; rt++) {
                const float* xb = &Xs[(wrow + rt * 16 + qr) * ST + kk + qc];
                a[rt][0] = __float_as_uint(xb[0]);
                a[rt][1] = __float_as_uint(xb[8 * ST]);
                a[rt][2] = __float_as_uint(xb[4]);
                a[rt][3] = __float_as_uint(xb[8 * ST + 4]);
            }
            unsigned b[NT][2];
#pragma unroll
            for (int ct = 0; ct < NT; ct++) {
                const float* wb = &Ws[(wcol + ct * 8 + qr) * ST + kk + qc];
                b[ct][0] = __float_as_uint(wb[0]);
                b[ct][1] = __float_as_uint(wb[4]);
            }
#pragma unroll
            for (int rt = 0; rt < 2; rt++)
#pragma unroll
                for (int ct = 0; ct < NT; ct++)
                    mma_tf32(acc[rt][ct], a[rt], b[ct]);
        }
        __syncthreads();
    }

    // epilogue: scale by dinv[row], float2 stores
#pragma unroll
    for (int rt = 0; rt < 2; rt++) {
        int r0 = row0 + wrow + rt * 16 + qr;
        int r1 = r0 + 8;
        float d0 = (r0 < n) ? g_dinv[r0] : 0.f;
        float d1 = (r1 < n) ? g_dinv[r1] : 0.f;
#pragma unroll
        for (int ct = 0; ct < NT; ct++) {
            int col = wcol + ct * 8 + qc * 2;
            if (r0 < n)
                *(float2*)&outS[(size_t)r0 * FOUT + col] =
                    make_float2(acc[rt][ct][0] * d0, acc[rt][ct][1] * d0);
            if (r1 < n)
                *(float2*)&outS[(size_t)r1 * FOUT + col] =
                    make_float2(acc[rt][ct][2] * d1, acc[rt][ct][3] * d1);
        }
    }
}

// ---------------- CSR aggregation (atomic-free, MLP-unrolled) ----------------
__global__ void agg1_kernel(int n) {
    int w = (blockIdx.x * blockDim.x + threadIdx.x) >> 5;
    if (w >= n) return;
    int lane = threadIdx.x & 31;
    int c = lane * 4;
    float4 acc = *(const float4*)&g_t1s[(size_t)w * F1 + c];   // self-loop
    int beg = g_rowptr[w];
    int cnt = g_cnt[w];
    int j = 0;
    for (; j + 4 <= cnt; j += 4) {
        int s0 = g_adj[beg + j + 0];
        int s1 = g_adj[beg + j + 1];
        int s2 = g_adj[beg + j + 2];
        int s3 = g_adj[beg + j + 3];
        float4 v0 = *(const float4*)&g_t1s[(size_t)s0 * F1 + c];
        float4 v1 = *(const float4*)&g_t1s[(size_t)s1 * F1 + c];
        float4 v2 = *(const float4*)&g_t1s[(size_t)s2 * F1 + c];
        float4 v3 = *(const float4*)&g_t1s[(size_t)s3 * F1 + c];
        acc.x += v0.x + v1.x + v2.x + v3.x;
        acc.y += v0.y + v1.y + v2.y + v3.y;
        acc.z += v0.z + v1.z + v2.z + v3.z;
        acc.w += v0.w + v1.w + v2.w + v3.w;
    }
    for (; j < cnt; j++) {
        int src = g_adj[beg + j];
        float4 v = *(const float4*)&g_t1s[(size_t)src * F1 + c];
        acc.x += v.x; acc.y += v.y; acc.z += v.z; acc.w += v.w;
    }
    float di = g_dinv[w];
    *(float4*)&g_agg1[(size_t)w * F1 + c] =
        make_float4(acc.x*di, acc.y*di, acc.z*di, acc.w*di);
}

__global__ void agg2_kernel(const float* __restrict__ b2, float* __restrict__ out, int n) {
    int h = (blockIdx.x * blockDim.x + threadIdx.x) >> 4;
    if (h >= n) return;
    int lane = threadIdx.x & 15;
    int c = lane * 4;
    float4 acc = *(const float4*)&g_t2s[(size_t)h * F2 + c];   // self-loop
    int beg = g_rowptr[h];
    int cnt = g_cnt[h];
    int j = 0;
    for (; j + 4 <= cnt; j += 4) {
        int s0 = g_adj[beg + j + 0];
        int s1 = g_adj[beg + j + 1];
        int s2 = g_adj[beg + j + 2];
        int s3 = g_adj[beg + j + 3];
        float4 v0 = *(const float4*)&g_t2s[(size_t)s0 * F2 + c];
        float4 v1 = *(const float4*)&g_t2s[(size_t)s1 * F2 + c];
        float4 v2 = *(const float4*)&g_t2s[(size_t)s2 * F2 + c];
        float4 v3 = *(const float4*)&g_t2s[(size_t)s3 * F2 + c];
        acc.x += v0.x + v1.x + v2.x + v3.x;
        acc.y += v0.y + v1.y + v2.y + v3.y;
        acc.z += v0.z + v1.z + v2.z + v3.z;
        acc.w += v0.w + v1.w + v2.w + v3.w;
    }
    for (; j < cnt; j++) {
        int src = g_adj[beg + j];
        float4 v = *(const float4*)&g_t2s[(size_t)src * F2 + c];
        acc.x += v.x; acc.y += v.y; acc.z += v.z; acc.w += v.w;
    }
    float di = g_dinv[h];
    *(float4*)&out[(size_t)h * F2 + c] =
        make_float4(acc.x*di + b2[c+0], acc.y*di + b2[c+1],
                    acc.z*di + b2[c+2], acc.w*di + b2[c+3]);
}

// ---------------- launch ----------------
extern "C" void kernel_launch(void* const* d_in, const int* in_sizes, int n_in,
                              void* d_out, int out_size) {
    const float* x  = (const float*)d_in[0];
    const void*  ei = d_in[1];
    const float* W1 = (const float*)d_in[2];
    const float* b1 = (const float*)d_in[3];
    const float* W2 = (const float*)d_in[4];
    const float* b2 = (const float*)d_in[5];
    float* out = (float*)d_out;

    const int n = in_sizes[0] / F1;       // 100000
    const int e = in_sizes[1] / 2;        // 1600000

    const int T = 256;
    // CSR build + norms
    detect_kernel<<<1, 256>>>(ei, n, e);
    zero_cnt_kernel<<<(n + T - 1) / T, T>>>(n);
    count_kernel<<<(e + T - 1) / T, T>>>(ei, e);
    dinv_kernel<<<(n + T - 1) / T, T>>>(n);
    scan_kernel<<<1, 1024>>>(n);
    fill_kernel<<<(e + T - 1) / T, T>>>(ei, e);

    // layer 1
    gemm_tc<true><<<(n + 127) / 128, 256>>>(x, W1, nullptr, n);
    agg1_kernel<<<(n * 32 + T - 1) / T, T>>>(n);

    // layer 2
    gemm_tc<false><<<(n + 127) / 128, 256>>>(nullptr, W2, b1, n);
    agg2_kernel<<<(n * 16 + T - 1) / T, T>>>(b2, out, n);
}